// round 10
// baseline (speedup 1.0000x reference)
#include <cuda_runtime.h>
#include <float.h>

#define BB 16
#define CL 512
#define QL 64
#define HH 768
#define NEG_INF (-1e30f)

// ---------------- scratch ----------------
__device__ __align__(16) float g_qp[BB * QL * HH];   // q @ W            [B,64,768]
__device__ __align__(16) float g_bq[BB * QL];        // q . b            [B,64]
__device__ __align__(16) float g_s [BB * CL * QL];   // raw logits       [B,512,64]
__device__ __align__(16) float g_s1[BB * CL * QL];   // row softmax      [B,512,64]
__device__ __align__(16) float g_s2[BB * CL * QL];   // col exp (unnorm) [B,512,64]
__device__ __align__(16) float g_cinv[BB * QL];      // 1/col-sum        [B,64]
__device__ __align__(16) float g_t [BB * QL * HH];   // s2^T @ c         [B,64,768]

// ---------------- bq[row] = q[row,:] . b ----------------
__global__ void bq_kernel(const float* __restrict__ q, const float* __restrict__ bias,
                          int rowOffset) {
    int row  = rowOffset + blockIdx.x * 8 + (threadIdx.x >> 5);
    int lane = threadIdx.x & 31;
    const float* qr = q + row * HH;
    float s = 0.f;
    for (int d = lane; d < HH; d += 32) s += qr[d] * bias[d];
#pragma unroll
    for (int o = 16; o; o >>= 1) s += __shfl_down_sync(0xffffffffu, s, o);
    if (lane == 0) g_bq[row] = s;
}

// =====================================================================
// GEMM core: 32x64x16 tiles, 256 threads, 2x4 micro, double-buffered.
// tx = tid&15 (cols tx4..+3), ty = tid>>4 (rows ty2=2*ty, +1).
// ar = LDS.64 (broadcast), br = LDS.128. 8 warps/CTA, large grids.
// =====================================================================

// ---------------- qp = q @ W   (M=1024, N=768, K=768) ----------------
__global__ void qp_gemm(const float* __restrict__ q, const float* __restrict__ W) {
    __shared__ __align__(16) float As[2][16][36];   // [k][m]
    __shared__ __align__(16) float Bs[2][16][68];   // [k][n]
    int tid = threadIdx.x;
    int tx = tid & 15, ty = tid >> 4;
    int tx4 = tx << 2, ty2 = ty << 1;
    int mBase = blockIdx.y * 32, nBase = blockIdx.x * 64;
    int lm = tid >> 3, lk2 = (tid & 7) << 1;       // A fill: 32m x 16k, float2/thr
    int bk = tid >> 4, bn4 = (tid & 15) << 2;      // B fill: 16k x 64n, float4/thr
    float acc[2][4] = {};

    float2 av = *(const float2*)(q + (mBase + lm) * HH + lk2);
    float4 bv = *(const float4*)(W + bk * HH + nBase + bn4);
    As[0][lk2][lm] = av.x; As[0][lk2 + 1][lm] = av.y;
    *(float4*)&Bs[0][bk][bn4] = bv;
    __syncthreads();
    int buf = 0;
    for (int kt = 0; kt < HH; kt += 16) {
        bool more = (kt + 16) < HH;
        float2 nav; float4 nbv;
        if (more) {
            nav = *(const float2*)(q + (mBase + lm) * HH + kt + 16 + lk2);
            nbv = *(const float4*)(W + (kt + 16 + bk) * HH + nBase + bn4);
        }
#pragma unroll
        for (int k = 0; k < 16; k++) {
            float2 ar = *(const float2*)&As[buf][k][ty2];
            float4 br = *(const float4*)&Bs[buf][k][tx4];
            acc[0][0] = fmaf(ar.x, br.x, acc[0][0]); acc[0][1] = fmaf(ar.x, br.y, acc[0][1]);
            acc[0][2] = fmaf(ar.x, br.z, acc[0][2]); acc[0][3] = fmaf(ar.x, br.w, acc[0][3]);
            acc[1][0] = fmaf(ar.y, br.x, acc[1][0]); acc[1][1] = fmaf(ar.y, br.y, acc[1][1]);
            acc[1][2] = fmaf(ar.y, br.z, acc[1][2]); acc[1][3] = fmaf(ar.y, br.w, acc[1][3]);
        }
        if (more) {
            int nb = buf ^ 1;
            As[nb][lk2][lm] = nav.x; As[nb][lk2 + 1][lm] = nav.y;
            *(float4*)&Bs[nb][bk][bn4] = nbv;
            __syncthreads();
            buf = nb;
        }
    }
#pragma unroll
    for (int i = 0; i < 2; i++) {
        float4 o = make_float4(acc[i][0], acc[i][1], acc[i][2], acc[i][3]);
        *(float4*)(g_qp + (mBase + ty2 + i) * HH + nBase + tx4) = o;
    }
}

// ---------------- s_gemm + fused row softmax ----------------
// 32x64x16, 256 thr, grid (16,16)=256 CTAs.
__global__ void s_gemm(const float* __restrict__ c, const int* __restrict__ q_mask) {
    __shared__ __align__(16) float As[2][16][36];   // c  [k][m]
    __shared__ __align__(16) float Bs[2][16][68];   // qp [k][j]
    int tid = threadIdx.x;
    int tx = tid & 15, ty = tid >> 4;
    int tx4 = tx << 2, ty2 = ty << 1;
    int b = blockIdx.y;
    int mBase = blockIdx.x * 32;
    const float* A = c + b * CL * HH;
    const float* Bt = g_qp + b * QL * HH;
    int lm = tid >> 3, lk2 = (tid & 7) << 1;       // A fill
    int lj = tid >> 2, lkb = (tid & 3) << 2;       // B fill: 64j x 16k, float4/thr
    float acc[2][4] = {};

    {
        float2 av = *(const float2*)(A + (mBase + lm) * HH + lk2);
        As[0][lk2][lm] = av.x; As[0][lk2 + 1][lm] = av.y;
        float4 bv = *(const float4*)(Bt + lj * HH + lkb);
        Bs[0][lkb + 0][lj] = bv.x; Bs[0][lkb + 1][lj] = bv.y;
        Bs[0][lkb + 2][lj] = bv.z; Bs[0][lkb + 3][lj] = bv.w;
    }
    __syncthreads();
    int buf = 0;
    for (int kt = 0; kt < HH; kt += 16) {
        bool more = (kt + 16) < HH;
        float2 nav; float4 nbv;
        if (more) {
            nav = *(const float2*)(A + (mBase + lm) * HH + kt + 16 + lk2);
            nbv = *(const float4*)(Bt + lj * HH + kt + 16 + lkb);
        }
#pragma unroll
        for (int k = 0; k < 16; k++) {
            float2 ar = *(const float2*)&As[buf][k][ty2];
            float4 br = *(const float4*)&Bs[buf][k][tx4];
            acc[0][0] = fmaf(ar.x, br.x, acc[0][0]); acc[0][1] = fmaf(ar.x, br.y, acc[0][1]);
            acc[0][2] = fmaf(ar.x, br.z, acc[0][2]); acc[0][3] = fmaf(ar.x, br.w, acc[0][3]);
            acc[1][0] = fmaf(ar.y, br.x, acc[1][0]); acc[1][1] = fmaf(ar.y, br.y, acc[1][1]);
            acc[1][2] = fmaf(ar.y, br.z, acc[1][2]); acc[1][3] = fmaf(ar.y, br.w, acc[1][3]);
        }
        if (more) {
            int nb = buf ^ 1;
            As[nb][lk2][lm] = nav.x; As[nb][lk2 + 1][lm] = nav.y;
            Bs[nb][lkb + 0][lj] = nbv.x; Bs[nb][lkb + 1][lj] = nbv.y;
            Bs[nb][lkb + 2][lj] = nbv.z; Bs[nb][lkb + 3][lj] = nbv.w;
            __syncthreads();
            buf = nb;
        }
    }
    // epilogue: bias, raw store, fused row softmax (16 threads/half-warp own a row)
    float4 bqv = *(const float4*)(g_bq + b * QL + tx4);
    int qm0 = q_mask[b * QL + tx4 + 0];
    int qm1 = q_mask[b * QL + tx4 + 1];
    int qm2 = q_mask[b * QL + tx4 + 2];
    int qm3 = q_mask[b * QL + tx4 + 3];
#pragma unroll
    for (int i = 0; i < 2; i++) {
        float v0 = acc[i][0] + bqv.x, v1 = acc[i][1] + bqv.y;
        float v2 = acc[i][2] + bqv.z, v3 = acc[i][3] + bqv.w;
        int row = b * CL + mBase + ty2 + i;
        *(float4*)(g_s + row * QL + tx4) = make_float4(v0, v1, v2, v3);
        float m0 = qm0 ? v0 : NEG_INF;
        float m1 = qm1 ? v1 : NEG_INF;
        float m2 = qm2 ? v2 : NEG_INF;
        float m3 = qm3 ? v3 : NEG_INF;
        float mx = fmaxf(fmaxf(m0, m1), fmaxf(m2, m3));
#pragma unroll
        for (int o = 8; o; o >>= 1) mx = fmaxf(mx, __shfl_xor_sync(0xffffffffu, mx, o));
        float e0 = __expf(m0 - mx), e1 = __expf(m1 - mx);
        float e2 = __expf(m2 - mx), e3 = __expf(m3 - mx);
        float s = e0 + e1 + e2 + e3;
#pragma unroll
        for (int o = 8; o; o >>= 1) s += __shfl_xor_sync(0xffffffffu, s, o);
        float inv = 1.f / s;
        *(float4*)(g_s1 + row * QL + tx4) = make_float4(e0 * inv, e1 * inv, e2 * inv, e3 * inv);
    }
}

// ---------------- colexp: per-batch column max + exp + 1/sum ----------------
// grid (16 b, 4 colquads); block 256 = 4 colgroups x 64 row-threads.
__global__ void colexp_kernel(const int* __restrict__ c_mask) {
    int b  = blockIdx.x;
    int cq = blockIdx.y;                 // 16-col block
    int tid = threadIdx.x;
    int cg = tid & 3;                    // float4 group within 16 cols
    int ry = tid >> 2;                   // 0..63
    int col0 = cq * 16 + cg * 4;
    __shared__ float4 red[64][4];
    const float* sp = g_s + b * CL * QL;
    const int*   mp = c_mask + b * CL;

    float4 mx = make_float4(NEG_INF, NEG_INF, NEG_INF, NEG_INF);
#pragma unroll
    for (int k = 0; k < 8; k++) {
        int r = ry + k * 64;
        float4 v = *(const float4*)(sp + r * QL + col0);
        if (!mp[r]) v = make_float4(NEG_INF, NEG_INF, NEG_INF, NEG_INF);
        mx.x = fmaxf(mx.x, v.x); mx.y = fmaxf(mx.y, v.y);
        mx.z = fmaxf(mx.z, v.z); mx.w = fmaxf(mx.w, v.w);
    }
    red[ry][cg] = mx;
    __syncthreads();
#pragma unroll
    for (int st = 32; st >= 1; st >>= 1) {
        if (ry < st) {
            float4 a = red[ry][cg], c2 = red[ry + st][cg];
            a.x = fmaxf(a.x, c2.x); a.y = fmaxf(a.y, c2.y);
            a.z = fmaxf(a.z, c2.z); a.w = fmaxf(a.w, c2.w);
            red[ry][cg] = a;
        }
        __syncthreads();
    }
    float4 cmax = red[0][cg];
    __syncthreads();

    float4 sm = make_float4(0.f, 0.f, 0.f, 0.f);
    float* op = g_s2 + b * CL * QL;
#pragma unroll
    for (int k = 0; k < 8; k++) {
        int r = ry + k * 64;
        float4 v = *(const float4*)(sp + r * QL + col0);
        if (!mp[r]) v = make_float4(NEG_INF, NEG_INF, NEG_INF, NEG_INF);
        float4 e;
        e.x = __expf(v.x - cmax.x); e.y = __expf(v.y - cmax.y);
        e.z = __expf(v.z - cmax.z); e.w = __expf(v.w - cmax.w);
        *(float4*)(op + r * QL + col0) = e;
        sm.x += e.x; sm.y += e.y; sm.z += e.z; sm.w += e.w;
    }
    red[ry][cg] = sm;
    __syncthreads();
#pragma unroll
    for (int st = 32; st >= 1; st >>= 1) {
        if (ry < st) {
            float4 a = red[ry][cg], c2 = red[ry + st][cg];
            a.x += c2.x; a.y += c2.y; a.z += c2.z; a.w += c2.w;
            red[ry][cg] = a;
        }
        __syncthreads();
    }
    if (ry == 0) {
        float4 s = red[0][cg];
        float4 inv = make_float4(1.f / s.x, 1.f / s.y, 1.f / s.z, 1.f / s.w);
        *(float4*)(g_cinv + b * QL + col0) = inv;
    }
}

// ---------------- t[b,j,h] = sum_c s2n[b,c,j] * c[b,c,h]  (M=64, N=768, K=512) ----------------
// 32x64x16, 256 thr; grid (12, 32): y -> (b = y>>1, jBase = (y&1)*32).
__global__ void t_gemm(const float* __restrict__ c) {
    __shared__ __align__(16) float As[2][16][36];   // [kc][j], scaled
    __shared__ __align__(16) float Bs[2][16][68];   // [kc][h]
    int tid = threadIdx.x;
    int tx = tid & 15, ty = tid >> 4;
    int tx4 = tx << 2, ty2 = ty << 1;
    int b = blockIdx.y >> 1;
    int jBase = (blockIdx.y & 1) * 32;
    int nBase = blockIdx.x * 64;
    int akc = tid >> 4, aj2 = (tid & 15) << 1;     // A fill: 16kc x 32j, float2/thr
    int bk = tid >> 4, bn4 = (tid & 15) << 2;      // B fill
    float2 inv2 = *(const float2*)(g_cinv + b * QL + jBase + aj2);
    float acc[2][4] = {};

    {
        float2 av = *(const float2*)(g_s2 + (b * CL + akc) * QL + jBase + aj2);
        av.x *= inv2.x; av.y *= inv2.y;
        *(float2*)&As[0][akc][aj2] = av;
        float4 bv = *(const float4*)(c + (b * CL + bk) * HH + nBase + bn4);
        *(float4*)&Bs[0][bk][bn4] = bv;
    }
    __syncthreads();
    int buf = 0;
    for (int kt = 0; kt < CL; kt += 16) {
        bool more = (kt + 16) < CL;
        float2 nav; float4 nbv;
        if (more) {
            nav = *(const float2*)(g_s2 + (b * CL + kt + 16 + akc) * QL + jBase + aj2);
            nav.x *= inv2.x; nav.y *= inv2.y;
            nbv = *(const float4*)(c + (b * CL + kt + 16 + bk) * HH + nBase + bn4);
        }
#pragma unroll
        for (int k = 0; k < 16; k++) {
            float2 ar = *(const float2*)&As[buf][k][ty2];
            float4 br = *(const float4*)&Bs[buf][k][tx4];
            acc[0][0] = fmaf(ar.x, br.x, acc[0][0]); acc[0][1] = fmaf(ar.x, br.y, acc[0][1]);
            acc[0][2] = fmaf(ar.x, br.z, acc[0][2]); acc[0][3] = fmaf(ar.x, br.w, acc[0][3]);
            acc[1][0] = fmaf(ar.y, br.x, acc[1][0]); acc[1][1] = fmaf(ar.y, br.y, acc[1][1]);
            acc[1][2] = fmaf(ar.y, br.z, acc[1][2]); acc[1][3] = fmaf(ar.y, br.w, acc[1][3]);
        }
        if (more) {
            int nb = buf ^ 1;
            *(float2*)&As[nb][akc][aj2] = nav;
            *(float4*)&Bs[nb][bk][bn4] = nbv;
            __syncthreads();
            buf = nb;
        }
    }
#pragma unroll
    for (int i = 0; i < 2; i++) {
        float4 o = make_float4(acc[i][0], acc[i][1], acc[i][2], acc[i][3]);
        *(float4*)(g_t + (b * QL + jBase + ty2 + i) * HH + nBase + tx4) = o;
    }
}

// ---------------- final: a = s1@q, bvec = s1@t, out = [c, a, c*a, c*bvec] ----------------
// grid (8, 16, 6): z-split 6 -> 768 CTAs. S1 stored transposed for LDS.128.
__global__ void final_kernel(const float* __restrict__ c, const float* __restrict__ q,
                             float* __restrict__ out) {
    __shared__ __align__(16) float S1T[64][68];  // [j][c]
    __shared__ __align__(16) float Buf[64][68];  // [j][h]
    int tid = threadIdx.x;
    int tx = tid & 15, ty = tid >> 4;
    int tx4 = tx << 2, ty4 = ty << 2;
    int b = blockIdx.y;
    int cBase = blockIdx.x * 64;
    int hStart = blockIdx.z * 128;

    int lr  = tid >> 2;            // 0..63
    int lcb = (tid & 3) << 2;      // 0,4,8,12

#pragma unroll
    for (int i = 0; i < 4; i++) {
        int lc = lcb + i * 16;
        float4 sv = *(const float4*)(g_s1 + (b * CL + cBase + lr) * QL + lc);
        S1T[lc + 0][lr] = sv.x; S1T[lc + 1][lr] = sv.y;
        S1T[lc + 2][lr] = sv.z; S1T[lc + 3][lr] = sv.w;
    }
    __syncthreads();

    const float* qb = q + b * QL * HH;
    const float* tb = g_t + b * QL * HH;
    const float* cb = c + b * CL * HH;
    float* ob = out + (size_t)(b * CL) * (4 * HH);

    for (int hc = hStart; hc < hStart + 128; hc += 64) {
        // ---- pass 1: a = s1 @ q ----
#pragma unroll
        for (int i = 0; i < 4; i++) {
            int lc = lcb + i * 16;
            float4 qv = *(const float4*)(qb + lr * HH + hc + lc);
            Buf[lr][lc + 0] = qv.x; Buf[lr][lc + 1] = qv.y;
            Buf[lr][lc + 2] = qv.z; Buf[lr][lc + 3] = qv.w;
        }
        __syncthreads();
        float acc[4][4] = {};
#pragma unroll 16
        for (int k = 0; k < 64; k++) {
            float4 ar = *(const float4*)&S1T[k][ty4];
            float4 br = *(const float4*)&Buf[k][tx4];
            acc[0][0] = fmaf(ar.x, br.x, acc[0][0]); acc[0][1] = fmaf(ar.x, br.y, acc[0][1]);
            acc[0][2] = fmaf(ar.x, br.z, acc[0][2]); acc[0][3] = fmaf(ar.x, br.w, acc[0][3]);
            acc[1][0] = fmaf(ar.y, br.x, acc[1][0]); acc[1][1] = fmaf(ar.y, br.y, acc[1][1]);
            acc[1][2] = fmaf(ar.y, br.z, acc[1][2]); acc[1][3] = fmaf(ar.y, br.w, acc[1][3]);
            acc[2][0] = fmaf(ar.z, br.x, acc[2][0]); acc[2][1] = fmaf(ar.z, br.y, acc[2][1]);
            acc[2][2] = fmaf(ar.z, br.z, acc[2][2]); acc[2][3] = fmaf(ar.z, br.w, acc[2][3]);
            acc[3][0] = fmaf(ar.w, br.x, acc[3][0]); acc[3][1] = fmaf(ar.w, br.y, acc[3][1]);
            acc[3][2] = fmaf(ar.w, br.z, acc[3][2]); acc[3][3] = fmaf(ar.w, br.w, acc[3][3]);
        }
#pragma unroll
        for (int i = 0; i < 4; i++) {
            int r = cBase + ty4 + i;
            float4 cv = *(const float4*)(cb + r * HH + hc + tx4);
            float4 a4 = make_float4(acc[i][0], acc[i][1], acc[i][2], acc[i][3]);
            float4 ca = make_float4(cv.x * a4.x, cv.y * a4.y, cv.z * a4.z, cv.w * a4.w);
            float* orow = ob + (size_t)r * (4 * HH);
            *(float4*)(orow + 0 * HH + hc + tx4) = cv;   // c
            *(float4*)(orow + 1 * HH + hc + tx4) = a4;   // a
            *(float4*)(orow + 2 * HH + hc + tx4) = ca;   // c*a
        }
        __syncthreads();
        // ---- pass 2: bvec = s1 @ t ----
#pragma unroll
        for (int i = 0; i < 4; i++) {
            int lc = lcb + i * 16;
            float4 tv = *(const float4*)(tb + lr * HH + hc + lc);
            Buf[lr][lc + 0] = tv.x; Buf[lr][lc + 1] = tv.y;
            Buf[lr][lc + 2] = tv.z; Buf[lr][lc + 3] = tv.w;
        }
        __syncthreads();
        float acc2[4][4] = {};
#pragma unroll 16
        for (int k = 0; k < 64; k++) {
            float4 ar = *(const float4*)&S1T[k][ty4];
            float4 br = *(const float4*)&Buf[k][tx4];
            acc2[0][0] = fmaf(ar.x, br.x, acc2[0][0]); acc2[0][1] = fmaf(ar.x, br.y, acc2[0][1]);
            acc2[0][2] = fmaf(ar.x, br.z, acc2[0][2]); acc2[0][3] = fmaf(ar.x, br.w, acc2[0][3]);
            acc2[1][0] = fmaf(ar.y, br.x, acc2[1][0]); acc2[1][1] = fmaf(ar.y, br.y, acc2[1][1]);
            acc2[1][2] = fmaf(ar.y, br.z, acc2[1][2]); acc2[1][3] = fmaf(ar.y, br.w, acc2[1][3]);
            acc2[2][0] = fmaf(ar.z, br.x, acc2[2][0]); acc2[2][1] = fmaf(ar.z, br.y, acc2[2][1]);
            acc2[2][2] = fmaf(ar.z, br.z, acc2[2][2]); acc2[2][3] = fmaf(ar.z, br.w, acc2[2][3]);
            acc2[3][0] = fmaf(ar.w, br.x, acc2[3][0]); acc2[3][1] = fmaf(ar.w, br.y, acc2[3][1]);
            acc2[3][2] = fmaf(ar.w, br.z, acc2[3][2]); acc2[3][3] = fmaf(ar.w, br.w, acc2[3][3]);
        }
#pragma unroll
        for (int i = 0; i < 4; i++) {
            int r = cBase + ty4 + i;
            float4 cv = *(const float4*)(cb + r * HH + hc + tx4);
            float4 cbv = make_float4(cv.x * acc2[i][0], cv.y * acc2[i][1],
                                     cv.z * acc2[i][2], cv.w * acc2[i][3]);
            float* orow = ob + (size_t)r * (4 * HH);
            *(float4*)(orow + 3 * HH + hc + tx4) = cbv;  // c*bvec
        }
        __syncthreads();
    }
}

extern "C" void kernel_launch(void* const* d_in, const int* in_sizes, int n_in,
                              void* d_out, int out_size) {
    (void)in_sizes; (void)n_in; (void)out_size;
    const float* c      = (const float*)d_in[0];
    const float* q      = (const float*)d_in[1];
    const int*   c_mask = (const int*)d_in[2];
    const int*   q_mask = (const int*)d_in[3];
    const float* W      = (const float*)d_in[4];
    const float* bias   = (const float*)d_in[5];
    float* out = (float*)d_out;

    bq_kernel    <<<64, 256>>>(q, bias, 0);
    bq_kernel    <<<64, 256>>>(q, bias, 512);
    qp_gemm      <<<dim3(12, 32), 256>>>(q, W);
    s_gemm       <<<dim3(16, 16), 256>>>(c, q_mask);   // profiled slot
    colexp_kernel<<<dim3(16, 4), 256>>>(c_mask);
    t_gemm       <<<dim3(12, 32), 256>>>(c);
    final_kernel <<<dim3(8, 16, 6), 256>>>(c, q, out);
}

// round 11
// speedup vs baseline: 1.0809x; 1.0809x over previous
#include <cuda_runtime.h>
#include <float.h>

#define BB 16
#define CL 512
#define QL 64
#define HH 768
#define NEG_INF (-1e30f)

// ---------------- scratch ----------------
__device__ __align__(16) float g_qp[BB * QL * HH];   // q @ W            [B,64,768]
__device__ __align__(16) float g_bq[BB * QL];        // q . b            [B,64]
__device__ __align__(16) float g_s [BB * CL * QL];   // raw logits       [B,512,64]
__device__ __align__(16) float g_s1[BB * CL * QL];   // row softmax      [B,512,64]
__device__ __align__(16) float g_s2[BB * CL * QL];   // col exp (unnorm) [B,512,64]
__device__ __align__(16) float g_cinv[BB * QL];      // 1/col-sum        [B,64]
__device__ __align__(16) float g_t [BB * QL * HH];   // s2^T @ c         [B,64,768]

// ---------------- bq[row] = q[row,:] . b ----------------
__global__ void bq_kernel(const float* __restrict__ q, const float* __restrict__ bias) {
    int row  = blockIdx.x * 8 + (threadIdx.x >> 5);
    int lane = threadIdx.x & 31;
    const float* qr = q + row * HH;
    float s = 0.f;
    for (int d = lane; d < HH; d += 32) s += qr[d] * bias[d];
#pragma unroll
    for (int o = 16; o; o >>= 1) s += __shfl_down_sync(0xffffffffu, s, o);
    if (lane == 0) g_bq[row] = s;
}

// ---------------- qp = q @ W   (M=1024, N=768, K=768) ----------------
// 64x64x16 tiles, 256 thr, 4x4 micro, double-buffered, LDS.128.
__global__ void qp_gemm(const float* __restrict__ q, const float* __restrict__ W) {
    __shared__ __align__(16) float As[2][16][68];   // [k][m]
    __shared__ __align__(16) float Bs[2][16][68];   // [k][n]
    int tid = threadIdx.x;
    int tx = tid & 15, ty = tid >> 4;
    int tx4 = tx << 2, ty4 = ty << 2;
    int mBase = blockIdx.y * 64, nBase = blockIdx.x * 64;
    int lm = tid >> 2, lk = (tid & 3) << 2;        // A fill (transpose)
    int bk = tid >> 4, bn4 = (tid & 15) << 2;      // B fill (direct)
    float acc[4][4] = {};

    float4 av = *(const float4*)(q + (mBase + lm) * HH + lk);
    float4 bv = *(const float4*)(W + bk * HH + nBase + bn4);
    As[0][lk + 0][lm] = av.x; As[0][lk + 1][lm] = av.y;
    As[0][lk + 2][lm] = av.z; As[0][lk + 3][lm] = av.w;
    *(float4*)&Bs[0][bk][bn4] = bv;
    __syncthreads();
    int buf = 0;
    for (int kt = 0; kt < HH; kt += 16) {
        bool more = (kt + 16) < HH;
        float4 nav, nbv;
        if (more) {
            nav = *(const float4*)(q + (mBase + lm) * HH + kt + 16 + lk);
            nbv = *(const float4*)(W + (kt + 16 + bk) * HH + nBase + bn4);
        }
#pragma unroll
        for (int k = 0; k < 16; k++) {
            float4 ar = *(const float4*)&As[buf][k][ty4];
            float4 br = *(const float4*)&Bs[buf][k][tx4];
            acc[0][0] = fmaf(ar.x, br.x, acc[0][0]); acc[0][1] = fmaf(ar.x, br.y, acc[0][1]);
            acc[0][2] = fmaf(ar.x, br.z, acc[0][2]); acc[0][3] = fmaf(ar.x, br.w, acc[0][3]);
            acc[1][0] = fmaf(ar.y, br.x, acc[1][0]); acc[1][1] = fmaf(ar.y, br.y, acc[1][1]);
            acc[1][2] = fmaf(ar.y, br.z, acc[1][2]); acc[1][3] = fmaf(ar.y, br.w, acc[1][3]);
            acc[2][0] = fmaf(ar.z, br.x, acc[2][0]); acc[2][1] = fmaf(ar.z, br.y, acc[2][1]);
            acc[2][2] = fmaf(ar.z, br.z, acc[2][2]); acc[2][3] = fmaf(ar.z, br.w, acc[2][3]);
            acc[3][0] = fmaf(ar.w, br.x, acc[3][0]); acc[3][1] = fmaf(ar.w, br.y, acc[3][1]);
            acc[3][2] = fmaf(ar.w, br.z, acc[3][2]); acc[3][3] = fmaf(ar.w, br.w, acc[3][3]);
        }
        if (more) {
            int nb = buf ^ 1;
            As[nb][lk + 0][lm] = nav.x; As[nb][lk + 1][lm] = nav.y;
            As[nb][lk + 2][lm] = nav.z; As[nb][lk + 3][lm] = nav.w;
            *(float4*)&Bs[nb][bk][bn4] = nbv;
            __syncthreads();
            buf = nb;
        }
    }
#pragma unroll
    for (int i = 0; i < 4; i++) {
        float4 o = make_float4(acc[i][0], acc[i][1], acc[i][2], acc[i][3]);
        *(float4*)(g_qp + (mBase + ty4 + i) * HH + nBase + tx4) = o;
    }
}

// ---------------- s_gemm + fused row softmax ----------------
// 64x64x16 tiles, 256 thr, 4x4 micro, LDS.128, grid (8,16)=128.
__global__ void s_gemm(const float* __restrict__ c, const int* __restrict__ q_mask) {
    __shared__ __align__(16) float As[2][16][68];   // c  [k][m]
    __shared__ __align__(16) float Bs[2][16][68];   // qp [k][j]
    int tid = threadIdx.x;
    int tx = tid & 15, ty = tid >> 4;
    int tx4 = tx << 2, ty4 = ty << 2;
    int b = blockIdx.y;
    int mBase = blockIdx.x * 64;
    const float* A = c + b * CL * HH;
    const float* Bt = g_qp + b * QL * HH;
    int lm = tid >> 2, lk = (tid & 3) << 2;
    float acc[4][4] = {};

    {
        float4 av = *(const float4*)(A + (mBase + lm) * HH + lk);
        float4 bv = *(const float4*)(Bt + lm * HH + lk);   // lm = j row
        As[0][lk + 0][lm] = av.x; As[0][lk + 1][lm] = av.y;
        As[0][lk + 2][lm] = av.z; As[0][lk + 3][lm] = av.w;
        Bs[0][lk + 0][lm] = bv.x; Bs[0][lk + 1][lm] = bv.y;
        Bs[0][lk + 2][lm] = bv.z; Bs[0][lk + 3][lm] = bv.w;
    }
    __syncthreads();
    int buf = 0;
    for (int kt = 0; kt < HH; kt += 16) {
        bool more = (kt + 16) < HH;
        float4 nav, nbv;
        if (more) {
            nav = *(const float4*)(A + (mBase + lm) * HH + kt + 16 + lk);
            nbv = *(const float4*)(Bt + lm * HH + kt + 16 + lk);
        }
#pragma unroll
        for (int k = 0; k < 16; k++) {
            float4 ar = *(const float4*)&As[buf][k][ty4];
            float4 br = *(const float4*)&Bs[buf][k][tx4];
            acc[0][0] = fmaf(ar.x, br.x, acc[0][0]); acc[0][1] = fmaf(ar.x, br.y, acc[0][1]);
            acc[0][2] = fmaf(ar.x, br.z, acc[0][2]); acc[0][3] = fmaf(ar.x, br.w, acc[0][3]);
            acc[1][0] = fmaf(ar.y, br.x, acc[1][0]); acc[1][1] = fmaf(ar.y, br.y, acc[1][1]);
            acc[1][2] = fmaf(ar.y, br.z, acc[1][2]); acc[1][3] = fmaf(ar.y, br.w, acc[1][3]);
            acc[2][0] = fmaf(ar.z, br.x, acc[2][0]); acc[2][1] = fmaf(ar.z, br.y, acc[2][1]);
            acc[2][2] = fmaf(ar.z, br.z, acc[2][2]); acc[2][3] = fmaf(ar.z, br.w, acc[2][3]);
            acc[3][0] = fmaf(ar.w, br.x, acc[3][0]); acc[3][1] = fmaf(ar.w, br.y, acc[3][1]);
            acc[3][2] = fmaf(ar.w, br.z, acc[3][2]); acc[3][3] = fmaf(ar.w, br.w, acc[3][3]);
        }
        if (more) {
            int nb = buf ^ 1;
            As[nb][lk + 0][lm] = nav.x; As[nb][lk + 1][lm] = nav.y;
            As[nb][lk + 2][lm] = nav.z; As[nb][lk + 3][lm] = nav.w;
            Bs[nb][lk + 0][lm] = nbv.x; Bs[nb][lk + 1][lm] = nbv.y;
            Bs[nb][lk + 2][lm] = nbv.z; Bs[nb][lk + 3][lm] = nbv.w;
            __syncthreads();
            buf = nb;
        }
    }
    // epilogue: bias, raw store, fused row softmax (16 threads own a row)
    float4 bqv = *(const float4*)(g_bq + b * QL + tx4);
    int qm0 = q_mask[b * QL + tx4 + 0];
    int qm1 = q_mask[b * QL + tx4 + 1];
    int qm2 = q_mask[b * QL + tx4 + 2];
    int qm3 = q_mask[b * QL + tx4 + 3];
#pragma unroll
    for (int i = 0; i < 4; i++) {
        float v0 = acc[i][0] + bqv.x, v1 = acc[i][1] + bqv.y;
        float v2 = acc[i][2] + bqv.z, v3 = acc[i][3] + bqv.w;
        int row = b * CL + mBase + ty4 + i;
        *(float4*)(g_s + row * QL + tx4) = make_float4(v0, v1, v2, v3);
        float m0 = qm0 ? v0 : NEG_INF;
        float m1 = qm1 ? v1 : NEG_INF;
        float m2 = qm2 ? v2 : NEG_INF;
        float m3 = qm3 ? v3 : NEG_INF;
        float mx = fmaxf(fmaxf(m0, m1), fmaxf(m2, m3));
#pragma unroll
        for (int o = 8; o; o >>= 1) mx = fmaxf(mx, __shfl_xor_sync(0xffffffffu, mx, o));
        float e0 = __expf(m0 - mx), e1 = __expf(m1 - mx);
        float e2 = __expf(m2 - mx), e3 = __expf(m3 - mx);
        float s = e0 + e1 + e2 + e3;
#pragma unroll
        for (int o = 8; o; o >>= 1) s += __shfl_xor_sync(0xffffffffu, s, o);
        float inv = 1.f / s;
        *(float4*)(g_s1 + row * QL + tx4) = make_float4(e0 * inv, e1 * inv, e2 * inv, e3 * inv);
    }
}

// ---------------- colexp: per-batch column max + exp + 1/sum ----------------
__global__ void colexp_kernel(const int* __restrict__ c_mask) {
    int b  = blockIdx.x;
    int cq = blockIdx.y;
    int tid = threadIdx.x;
    int cg = tid & 3;
    int ry = tid >> 2;                   // 0..63
    int col0 = cq * 16 + cg * 4;
    __shared__ float4 red[64][4];
    const float* sp = g_s + b * CL * QL;
    const int*   mp = c_mask + b * CL;

    float4 mx = make_float4(NEG_INF, NEG_INF, NEG_INF, NEG_INF);
#pragma unroll
    for (int k = 0; k < 8; k++) {
        int r = ry + k * 64;
        float4 v = *(const float4*)(sp + r * QL + col0);
        if (!mp[r]) v = make_float4(NEG_INF, NEG_INF, NEG_INF, NEG_INF);
        mx.x = fmaxf(mx.x, v.x); mx.y = fmaxf(mx.y, v.y);
        mx.z = fmaxf(mx.z, v.z); mx.w = fmaxf(mx.w, v.w);
    }
    red[ry][cg] = mx;
    __syncthreads();
#pragma unroll
    for (int st = 32; st >= 1; st >>= 1) {
        if (ry < st) {
            float4 a = red[ry][cg], c2 = red[ry + st][cg];
            a.x = fmaxf(a.x, c2.x); a.y = fmaxf(a.y, c2.y);
            a.z = fmaxf(a.z, c2.z); a.w = fmaxf(a.w, c2.w);
            red[ry][cg] = a;
        }
        __syncthreads();
    }
    float4 cmax = red[0][cg];
    __syncthreads();

    float4 sm = make_float4(0.f, 0.f, 0.f, 0.f);
    float* op = g_s2 + b * CL * QL;
#pragma unroll
    for (int k = 0; k < 8; k++) {
        int r = ry + k * 64;
        float4 v = *(const float4*)(sp + r * QL + col0);
        if (!mp[r]) v = make_float4(NEG_INF, NEG_INF, NEG_INF, NEG_INF);
        float4 e;
        e.x = __expf(v.x - cmax.x); e.y = __expf(v.y - cmax.y);
        e.z = __expf(v.z - cmax.z); e.w = __expf(v.w - cmax.w);
        *(float4*)(op + r * QL + col0) = e;
        sm.x += e.x; sm.y += e.y; sm.z += e.z; sm.w += e.w;
    }
    red[ry][cg] = sm;
    __syncthreads();
#pragma unroll
    for (int st = 32; st >= 1; st >>= 1) {
        if (ry < st) {
            float4 a = red[ry][cg], c2 = red[ry + st][cg];
            a.x += c2.x; a.y += c2.y; a.z += c2.z; a.w += c2.w;
            red[ry][cg] = a;
        }
        __syncthreads();
    }
    if (ry == 0) {
        float4 s = red[0][cg];
        float4 inv = make_float4(1.f / s.x, 1.f / s.y, 1.f / s.z, 1.f / s.w);
        *(float4*)(g_cinv + b * QL + col0) = inv;
    }
}

// ---------------- t[b,j,h] = sum_c s2n[b,c,j] * c[b,c,h]  (M=64, N=768, K=512) ----------------
__global__ void t_gemm(const float* __restrict__ c) {
    __shared__ __align__(16) float As[2][16][68];   // [kc][j], scaled
    __shared__ __align__(16) float Bs[2][16][68];   // [kc][h]
    int tid = threadIdx.x;
    int tx = tid & 15, ty = tid >> 4;
    int tx4 = tx << 2, ty4 = ty << 2;
    int b = blockIdx.y;
    int nBase = blockIdx.x * 64;
    int lc = tid >> 4, lj4 = (tid & 15) << 2;
    int bk = tid >> 4, bn4 = (tid & 15) << 2;
    float4 inv4 = *(const float4*)(g_cinv + b * QL + lj4);
    float acc[4][4] = {};

    float4 av = *(const float4*)(g_s2 + (b * CL + lc) * QL + lj4);
    av.x *= inv4.x; av.y *= inv4.y; av.z *= inv4.z; av.w *= inv4.w;
    float4 bv = *(const float4*)(c + (b * CL + bk) * HH + nBase + bn4);
    *(float4*)&As[0][lc][lj4] = av;
    *(float4*)&Bs[0][bk][bn4] = bv;
    __syncthreads();
    int buf = 0;
    for (int kt = 0; kt < CL; kt += 16) {
        bool more = (kt + 16) < CL;
        float4 nav, nbv;
        if (more) {
            nav = *(const float4*)(g_s2 + (b * CL + kt + 16 + lc) * QL + lj4);
            nav.x *= inv4.x; nav.y *= inv4.y; nav.z *= inv4.z; nav.w *= inv4.w;
            nbv = *(const float4*)(c + (b * CL + kt + 16 + bk) * HH + nBase + bn4);
        }
#pragma unroll
        for (int k = 0; k < 16; k++) {
            float4 ar = *(const float4*)&As[buf][k][ty4];
            float4 br = *(const float4*)&Bs[buf][k][tx4];
            acc[0][0] = fmaf(ar.x, br.x, acc[0][0]); acc[0][1] = fmaf(ar.x, br.y, acc[0][1]);
            acc[0][2] = fmaf(ar.x, br.z, acc[0][2]); acc[0][3] = fmaf(ar.x, br.w, acc[0][3]);
            acc[1][0] = fmaf(ar.y, br.x, acc[1][0]); acc[1][1] = fmaf(ar.y, br.y, acc[1][1]);
            acc[1][2] = fmaf(ar.y, br.z, acc[1][2]); acc[1][3] = fmaf(ar.y, br.w, acc[1][3]);
            acc[2][0] = fmaf(ar.z, br.x, acc[2][0]); acc[2][1] = fmaf(ar.z, br.y, acc[2][1]);
            acc[2][2] = fmaf(ar.z, br.z, acc[2][2]); acc[2][3] = fmaf(ar.z, br.w, acc[2][3]);
            acc[3][0] = fmaf(ar.w, br.x, acc[3][0]); acc[3][1] = fmaf(ar.w, br.y, acc[3][1]);
            acc[3][2] = fmaf(ar.w, br.z, acc[3][2]); acc[3][3] = fmaf(ar.w, br.w, acc[3][3]);
        }
        if (more) {
            int nb = buf ^ 1;
            *(float4*)&As[nb][lc][lj4] = nav;
            *(float4*)&Bs[nb][bk][bn4] = nbv;
            __syncthreads();
            buf = nb;
        }
    }
#pragma unroll
    for (int i = 0; i < 4; i++) {
        float4 o = make_float4(acc[i][0], acc[i][1], acc[i][2], acc[i][3]);
        *(float4*)(g_t + (b * QL + ty4 + i) * HH + nBase + tx4) = o;
    }
}

// ---------------- final: a = s1@q, bvec = s1@t, out = [c, a, c*a, c*bvec] ----------------
__global__ void final_kernel(const float* __restrict__ c, const float* __restrict__ q,
                             float* __restrict__ out) {
    __shared__ __align__(16) float S1T[64][68];  // [j][c]
    __shared__ __align__(16) float Buf[64][68];  // [j][h]
    int tid = threadIdx.x;
    int tx = tid & 15, ty = tid >> 4;
    int tx4 = tx << 2, ty4 = ty << 2;
    int b = blockIdx.y;
    int cBase = blockIdx.x * 64;
    int hStart = blockIdx.z * 128;

    int lr  = tid >> 2;            // 0..63
    int lcb = (tid & 3) << 2;      // 0,4,8,12

#pragma unroll
    for (int i = 0; i < 4; i++) {
        int lc = lcb + i * 16;
        float4 sv = *(const float4*)(g_s1 + (b * CL + cBase + lr) * QL + lc);
        S1T[lc + 0][lr] = sv.x; S1T[lc + 1][lr] = sv.y;
        S1T[lc + 2][lr] = sv.z; S1T[lc + 3][lr] = sv.w;
    }
    __syncthreads();

    const float* qb = q + b * QL * HH;
    const float* tb = g_t + b * QL * HH;
    const float* cb = c + b * CL * HH;
    float* ob = out + (size_t)(b * CL) * (4 * HH);

    for (int hc = hStart; hc < hStart + 128; hc += 64) {
        // ---- pass 1: a = s1 @ q ----
#pragma unroll
        for (int i = 0; i < 4; i++) {
            int lc = lcb + i * 16;
            float4 qv = *(const float4*)(qb + lr * HH + hc + lc);
            Buf[lr][lc + 0] = qv.x; Buf[lr][lc + 1] = qv.y;
            Buf[lr][lc + 2] = qv.z; Buf[lr][lc + 3] = qv.w;
        }
        __syncthreads();
        float acc[4][4] = {};
#pragma unroll 16
        for (int k = 0; k < 64; k++) {
            float4 ar = *(const float4*)&S1T[k][ty4];
            float4 br = *(const float4*)&Buf[k][tx4];
            acc[0][0] = fmaf(ar.x, br.x, acc[0][0]); acc[0][1] = fmaf(ar.x, br.y, acc[0][1]);
            acc[0][2] = fmaf(ar.x, br.z, acc[0][2]); acc[0][3] = fmaf(ar.x, br.w, acc[0][3]);
            acc[1][0] = fmaf(ar.y, br.x, acc[1][0]); acc[1][1] = fmaf(ar.y, br.y, acc[1][1]);
            acc[1][2] = fmaf(ar.y, br.z, acc[1][2]); acc[1][3] = fmaf(ar.y, br.w, acc[1][3]);
            acc[2][0] = fmaf(ar.z, br.x, acc[2][0]); acc[2][1] = fmaf(ar.z, br.y, acc[2][1]);
            acc[2][2] = fmaf(ar.z, br.z, acc[2][2]); acc[2][3] = fmaf(ar.z, br.w, acc[2][3]);
            acc[3][0] = fmaf(ar.w, br.x, acc[3][0]); acc[3][1] = fmaf(ar.w, br.y, acc[3][1]);
            acc[3][2] = fmaf(ar.w, br.z, acc[3][2]); acc[3][3] = fmaf(ar.w, br.w, acc[3][3]);
        }
#pragma unroll
        for (int i = 0; i < 4; i++) {
            int r = cBase + ty4 + i;
            float4 cv = *(const float4*)(cb + r * HH + hc + tx4);
            float4 a4 = make_float4(acc[i][0], acc[i][1], acc[i][2], acc[i][3]);
            float4 ca = make_float4(cv.x * a4.x, cv.y * a4.y, cv.z * a4.z, cv.w * a4.w);
            float* orow = ob + (size_t)r * (4 * HH);
            *(float4*)(orow + 0 * HH + hc + tx4) = cv;   // c
            *(float4*)(orow + 1 * HH + hc + tx4) = a4;   // a
            *(float4*)(orow + 2 * HH + hc + tx4) = ca;   // c*a
        }
        __syncthreads();
        // ---- pass 2: bvec = s1 @ t ----
#pragma unroll
        for (int i = 0; i < 4; i++) {
            int lc = lcb + i * 16;
            float4 tv = *(const float4*)(tb + lr * HH + hc + lc);
            Buf[lr][lc + 0] = tv.x; Buf[lr][lc + 1] = tv.y;
            Buf[lr][lc + 2] = tv.z; Buf[lr][lc + 3] = tv.w;
        }
        __syncthreads();
        float acc2[4][4] = {};
#pragma unroll 16
        for (int k = 0; k < 64; k++) {
            float4 ar = *(const float4*)&S1T[k][ty4];
            float4 br = *(const float4*)&Buf[k][tx4];
            acc2[0][0] = fmaf(ar.x, br.x, acc2[0][0]); acc2[0][1] = fmaf(ar.x, br.y, acc2[0][1]);
            acc2[0][2] = fmaf(ar.x, br.z, acc2[0][2]); acc2[0][3] = fmaf(ar.x, br.w, acc2[0][3]);
            acc2[1][0] = fmaf(ar.y, br.x, acc2[1][0]); acc2[1][1] = fmaf(ar.y, br.y, acc2[1][1]);
            acc2[1][2] = fmaf(ar.y, br.z, acc2[1][2]); acc2[1][3] = fmaf(ar.y, br.w, acc2[1][3]);
            acc2[2][0] = fmaf(ar.z, br.x, acc2[2][0]); acc2[2][1] = fmaf(ar.z, br.y, acc2[2][1]);
            acc2[2][2] = fmaf(ar.z, br.z, acc2[2][2]); acc2[2][3] = fmaf(ar.z, br.w, acc2[2][3]);
            acc2[3][0] = fmaf(ar.w, br.x, acc2[3][0]); acc2[3][1] = fmaf(ar.w, br.y, acc2[3][1]);
            acc2[3][2] = fmaf(ar.w, br.z, acc2[3][2]); acc2[3][3] = fmaf(ar.w, br.w, acc2[3][3]);
        }
#pragma unroll
        for (int i = 0; i < 4; i++) {
            int r = cBase + ty4 + i;
            float4 cv = *(const float4*)(cb + r * HH + hc + tx4);
            float4 cbv = make_float4(cv.x * acc2[i][0], cv.y * acc2[i][1],
                                     cv.z * acc2[i][2], cv.w * acc2[i][3]);
            float* orow = ob + (size_t)r * (4 * HH);
            *(float4*)(orow + 3 * HH + hc + tx4) = cbv;  // c*bvec
        }
        __syncthreads();
    }
}

extern "C" void kernel_launch(void* const* d_in, const int* in_sizes, int n_in,
                              void* d_out, int out_size) {
    (void)in_sizes; (void)n_in; (void)out_size;
    const float* c      = (const float*)d_in[0];
    const float* q      = (const float*)d_in[1];
    const int*   c_mask = (const int*)d_in[2];
    const int*   q_mask = (const int*)d_in[3];
    const float* W      = (const float*)d_in[4];
    const float* bias   = (const float*)d_in[5];
    float* out = (float*)d_out;

    bq_kernel    <<<128, 256>>>(q, bias);
    qp_gemm      <<<dim3(12, 16), 256>>>(q, W);
    s_gemm       <<<dim3(8, 16), 256>>>(c, q_mask);
    colexp_kernel<<<dim3(16, 4), 256>>>(c_mask);
    t_gemm       <<<dim3(12, 16), 256>>>(c);
    final_kernel <<<dim3(8, 16, 6), 256>>>(c, q, out);
}